// round 3
// baseline (speedup 1.0000x reference)
#include <cuda_runtime.h>
#include <cuda_fp16.h>
#include <cstdint>
#include <cmath>

// Problem constants
#define NB 64          // batch
#define NS 16          // steps
#define NO 31          // opcodes
#define ND 1024        // hidden dim
#define KTOT (NO*ND)   // 31744  GEMM reduction dim
#define KSPLIT 62
#define KCH (KTOT/KSPLIT)  // 512
#define BK 32
#define NIT (KCH/BK)       // 16
#define BN 128
#define NTILES (ND/BN)     // 8
#define STAGES 3

// ---------------- device scratch (static globals: allocation-free) ----------------
__device__ __half  g_Kh[(size_t)KTOT * ND];        // 65 MB fp16 kernels, [kk][k]
__device__ __half  g_A[(size_t)NB * KTOT];         // 4 MB  A[b][o*1024+d] = w*h
__device__ float   g_partial[KSPLIT * NB * ND];    // 16.25 MB  split-K partials
__device__ float   g_h[NB * ND];                   // fp32 hidden state
__device__ float   g_w[NS][NB][NO];                // softmax weights per step
__device__ float   g_gate[NS][NB];                 // sigmoid gates per step

// ---------------- helpers ----------------
__device__ __forceinline__ uint32_t smem_u32(const void* p) {
    return (uint32_t)__cvta_generic_to_shared(p);
}
__device__ __forceinline__ void cp_async16(uint32_t dst, const void* src) {
    asm volatile("cp.async.cg.shared.global [%0], [%1], 16;\n" :: "r"(dst), "l"(src));
}
__device__ __forceinline__ void cp_commit() {
    asm volatile("cp.async.commit_group;\n");
}
__device__ __forceinline__ void cp_wait1() {
    asm volatile("cp.async.wait_group 1;\n");
}
__device__ __forceinline__ void ldm_x4(uint32_t* r, uint32_t addr) {
    asm volatile("ldmatrix.sync.aligned.m8n8.x4.shared.b16 {%0,%1,%2,%3}, [%4];\n"
                 : "=r"(r[0]), "=r"(r[1]), "=r"(r[2]), "=r"(r[3]) : "r"(addr));
}
__device__ __forceinline__ void ldm_x4t(uint32_t* r, uint32_t addr) {
    asm volatile("ldmatrix.sync.aligned.m8n8.x4.trans.shared.b16 {%0,%1,%2,%3}, [%4];\n"
                 : "=r"(r[0]), "=r"(r[1]), "=r"(r[2]), "=r"(r[3]) : "r"(addr));
}
__device__ __forceinline__ void mma16816(float* c, const uint32_t* a, uint32_t b0, uint32_t b1) {
    asm volatile(
        "mma.sync.aligned.m16n8k16.row.col.f32.f16.f16.f32 "
        "{%0,%1,%2,%3}, {%4,%5,%6,%7}, {%8,%9}, {%0,%1,%2,%3};\n"
        : "+f"(c[0]), "+f"(c[1]), "+f"(c[2]), "+f"(c[3])
        : "r"(a[0]), "r"(a[1]), "r"(a[2]), "r"(a[3]), "r"(b0), "r"(b1));
}

// ---------------- prep: softmax weights + gates ----------------
__global__ void prep_kernel(const float* __restrict__ logits,
                            const float* __restrict__ operands) {
    int bs = blockIdx.x;          // b*NS + s
    int b = bs >> 4, s = bs & 15;
    int lane = threadIdx.x;
    float v = (lane < NO) ? logits[bs * NO + lane] : -INFINITY;
    float m = v;
    #pragma unroll
    for (int off = 16; off > 0; off >>= 1)
        m = fmaxf(m, __shfl_xor_sync(0xffffffffu, m, off));
    float e = (lane < NO) ? expf(v - m) : 0.0f;
    float sum = e;
    #pragma unroll
    for (int off = 16; off > 0; off >>= 1)
        sum += __shfl_xor_sync(0xffffffffu, sum, off);
    if (lane < NO) g_w[s][b][lane] = e / sum;
    if (lane == 0) g_gate[s][b] = 1.0f / (1.0f + expf(-operands[bs * 4 + 3]));
}

// ---------------- convert op_kernels fp32 -> fp16 ----------------
__global__ void convert_kernel(const float* __restrict__ K) {
    size_t i = ((size_t)blockIdx.x * blockDim.x + threadIdx.x) * 8;
    float4 f0 = *(const float4*)(K + i);
    float4 f1 = *(const float4*)(K + i + 4);
    __half2* dst = (__half2*)(g_Kh + i);
    dst[0] = __floats2half2_rn(f0.x, f0.y);
    dst[1] = __floats2half2_rn(f0.z, f0.w);
    dst[2] = __floats2half2_rn(f1.x, f1.y);
    dst[3] = __floats2half2_rn(f1.z, f1.w);
}

// ---------------- GEMM: transformed = A @ Kh  (split-K into g_partial) ----------------
// grid (NTILES, KSPLIT) = (8,62) = 496 CTAs, 256 threads. M=64, N=128 per CTA, K-chunk 512.
__global__ __launch_bounds__(256) void gemm_step_kernel() {
    const int ntile = blockIdx.x;
    const int ks = blockIdx.y;
    const int tid = threadIdx.x;
    const int wid = tid >> 5, lane = tid & 31;
    const int wm = wid & 1, wn = wid >> 1;   // 2 x 4 warp grid, 32x32 per warp

    __shared__ __half As[STAGES][64 * 40];   // 32 used cols, stride 40 (conflict-free)
    __shared__ __half Bs[STAGES][32 * 136];  // 128 used cols, stride 136 (conflict-free)

    float c[2][4][4];
    #pragma unroll
    for (int i = 0; i < 2; i++)
        #pragma unroll
        for (int j = 0; j < 4; j++)
            #pragma unroll
            for (int q = 0; q < 4; q++) c[i][j][q] = 0.0f;

    const int k0 = ks * KCH;
    const int nbase = ntile * BN;

    // tile loaders
    const int arow = tid >> 2, ach = tid & 3;          // A: 64 rows x 4 chunks
    const int brow = tid >> 4, bch = tid & 15;         // B: 16 rows x 16 chunks (x2)

    #define LOAD_TILES(buf, kg) do {                                            \
        cp_async16(smem_u32(&As[buf][arow * 40 + ach * 8]),                     \
                   g_A + (size_t)arow * KTOT + (kg) + ach * 8);                 \
        cp_async16(smem_u32(&Bs[buf][brow * 136 + bch * 8]),                    \
                   g_Kh + (size_t)((kg) + brow) * ND + nbase + bch * 8);        \
        cp_async16(smem_u32(&Bs[buf][(brow + 16) * 136 + bch * 8]),             \
                   g_Kh + (size_t)((kg) + brow + 16) * ND + nbase + bch * 8);   \
    } while (0)

    LOAD_TILES(0, k0);
    cp_commit();
    LOAD_TILES(1, k0 + BK);
    cp_commit();

    for (int it = 0; it < NIT; ++it) {
        const int buf = it % STAGES;
        cp_wait1();          // stage `it` resident (all but newest group done)
        __syncthreads();

        // issue load for stage it+2 (into the buffer freed at end of it-1)
        if (it + 2 < NIT) {
            LOAD_TILES((it + 2) % STAGES, k0 + (it + 2) * BK);
        }
        cp_commit();         // always commit (possibly empty) to keep group count uniform

        #pragma unroll
        for (int kh = 0; kh < 2; ++kh) {
            uint32_t a[2][4];
            #pragma unroll
            for (int mf = 0; mf < 2; ++mf) {
                uint32_t addr = smem_u32(
                    &As[buf][(wm * 32 + mf * 16 + (lane & 15)) * 40 + kh * 16 + (lane >> 4) * 8]);
                ldm_x4(a[mf], addr);
            }
            uint32_t bb[2][4];
            #pragma unroll
            for (int np = 0; np < 2; ++np) {
                uint32_t addr = smem_u32(
                    &Bs[buf][(kh * 16 + (lane & 15)) * 136 + wn * 32 + np * 16 + (lane >> 4) * 8]);
                ldm_x4t(bb[np], addr);
            }
            #pragma unroll
            for (int mf = 0; mf < 2; ++mf)
                #pragma unroll
                for (int nf = 0; nf < 4; ++nf)
                    mma16816(c[mf][nf], a[mf], bb[nf >> 1][(nf & 1) * 2], bb[nf >> 1][(nf & 1) * 2 + 1]);
        }
        __syncthreads();
    }

    // epilogue: write this split's partial
    float* pp = g_partial + ((size_t)ks * NB * ND);
    #pragma unroll
    for (int mf = 0; mf < 2; ++mf) {
        #pragma unroll
        for (int nf = 0; nf < 4; ++nf) {
            int m = wm * 32 + mf * 16 + (lane >> 2);
            int n = nbase + wn * 32 + nf * 8 + (lane & 3) * 2;
            pp[(size_t)m * ND + n]           = c[mf][nf][0];
            pp[(size_t)m * ND + n + 1]       = c[mf][nf][1];
            pp[(size_t)(m + 8) * ND + n]     = c[mf][nf][2];
            pp[(size_t)(m + 8) * ND + n + 1] = c[mf][nf][3];
        }
    }
}

// ---------------- update: reduce partials, gate, build next A ----------------
// grid (NB, 2) x 256 threads; each thread owns 2 consecutive d.
// t = -1: init. t = 15: final (write d_out).
__global__ void update_kernel(const float* __restrict__ signal,
                              float* __restrict__ out, int t) {
    const int b = blockIdx.x;
    const int d2 = blockIdx.y * 256 + threadIdx.x;   // pair index, 0..511
    const int d = d2 * 2;
    const bool last = (t == NS - 1);

    __shared__ float wsh[NO];
    if (!last && threadIdx.x < NO) wsh[threadIdx.x] = g_w[t + 1][b][threadIdx.x];

    float2 hn;
    if (t < 0) {
        hn = *(const float2*)(signal + b * ND + d);
    } else {
        float2 tr = make_float2(0.0f, 0.0f);
        #pragma unroll
        for (int ks = 0; ks < KSPLIT; ++ks) {
            float2 p = *(const float2*)(g_partial + (size_t)ks * NB * ND + b * ND + d);
            tr.x += p.x;
            tr.y += p.y;
        }
        float g = g_gate[t][b];
        float2 h = *(const float2*)(g_h + b * ND + d);
        hn.x = g * tr.x + (1.0f - g) * h.x;
        hn.y = g * tr.y + (1.0f - g) * h.y;
    }
    __syncthreads();

    if (last) {
        *(float2*)(out + b * ND + d) = hn;
    } else {
        *(float2*)(g_h + b * ND + d) = hn;
        #pragma unroll
        for (int o = 0; o < NO; ++o) {
            float w = wsh[o];
            *(__half2*)(g_A + (size_t)b * KTOT + o * ND + d) =
                __floats2half2_rn(w * hn.x, w * hn.y);
        }
    }
}

// ---------------- launch ----------------
extern "C" void kernel_launch(void* const* d_in, const int* in_sizes, int n_in,
                              void* d_out, int out_size) {
    const float* logits   = (const float*)d_in[0];  // (64,16,31)
    const float* operands = (const float*)d_in[1];  // (64,16,4)
    const float* signal   = (const float*)d_in[2];  // (64,1024)
    const float* opk      = (const float*)d_in[3];  // (31,1024,1024)
    float* out = (float*)d_out;                     // (64,1024)

    prep_kernel<<<NB * NS, 32>>>(logits, operands);
    convert_kernel<<<(KTOT * ND) / 8 / 256, 256>>>(opk);
    update_kernel<<<dim3(NB, 2), 256>>>(signal, out, -1);   // init h + A for step 0

    for (int t = 0; t < NS; ++t) {
        gemm_step_kernel<<<dim3(NTILES, KSPLIT), 256>>>();
        update_kernel<<<dim3(NB, 2), 256>>>(signal, out, t);
    }
}

// round 4
// speedup vs baseline: 1.1666x; 1.1666x over previous
#include <cuda_runtime.h>
#include <cuda_fp16.h>
#include <cstdint>
#include <cmath>

// Problem constants
#define NB 64          // batch
#define NS 16          // steps
#define NO 31          // opcodes
#define ND 1024        // hidden dim
#define KTOT (NO*ND)   // 31744
#define KCH ND         // 1024: one opcode per K-split
#define BK 32
#define NIT (KCH/BK)   // 32
#define BN 128
#define NTILES (ND/BN) // 8
#define STAGES 3
#define NCTA (NTILES*NO)   // 248

// ---------------- device scratch ----------------
__device__ __half  g_Kh[(size_t)KTOT * ND];        // 65 MB fp16 kernels [o*1024+d][n]
__device__ __half  g_hh[NB * ND];                  // fp16 hidden (GEMM A operand)
__device__ float   g_h[NB * ND];                   // fp32 hidden state
__device__ float   g_partial[NO * NB * ND];        // per-opcode partials (w applied)
__device__ float   g_w[NS][NB][NO];                // softmax weights
__device__ float   g_gate[NS][NB];                 // sigmoid gates
__device__ volatile unsigned g_gen;                // barrier generation (monotone)
__device__ unsigned g_cnt;                         // barrier arrive counter

// ---------------- helpers ----------------
__device__ __forceinline__ uint32_t smem_u32(const void* p) {
    return (uint32_t)__cvta_generic_to_shared(p);
}
__device__ __forceinline__ void cp_async16(uint32_t dst, const void* src) {
    asm volatile("cp.async.cg.shared.global [%0], [%1], 16;\n" :: "r"(dst), "l"(src));
}
__device__ __forceinline__ void cp_commit() {
    asm volatile("cp.async.commit_group;\n");
}
__device__ __forceinline__ void cp_wait1() {
    asm volatile("cp.async.wait_group 1;\n");
}
__device__ __forceinline__ void ldm_x4(uint32_t* r, uint32_t addr) {
    asm volatile("ldmatrix.sync.aligned.m8n8.x4.shared.b16 {%0,%1,%2,%3}, [%4];\n"
                 : "=r"(r[0]), "=r"(r[1]), "=r"(r[2]), "=r"(r[3]) : "r"(addr));
}
__device__ __forceinline__ void ldm_x4t(uint32_t* r, uint32_t addr) {
    asm volatile("ldmatrix.sync.aligned.m8n8.x4.trans.shared.b16 {%0,%1,%2,%3}, [%4];\n"
                 : "=r"(r[0]), "=r"(r[1]), "=r"(r[2]), "=r"(r[3]) : "r"(addr));
}
__device__ __forceinline__ void mma16816(float* c, const uint32_t* a, uint32_t b0, uint32_t b1) {
    asm volatile(
        "mma.sync.aligned.m16n8k16.row.col.f32.f16.f16.f32 "
        "{%0,%1,%2,%3}, {%4,%5,%6,%7}, {%8,%9}, {%0,%1,%2,%3};\n"
        : "+f"(c[0]), "+f"(c[1]), "+f"(c[2]), "+f"(c[3])
        : "r"(a[0]), "r"(a[1]), "r"(a[2]), "r"(a[3]), "r"(b0), "r"(b1));
}

// Replay-safe grid barrier: wait until g_gen reaches `target`.
__device__ __forceinline__ void grid_barrier(unsigned target) {
    __syncthreads();
    if (threadIdx.x == 0) {
        __threadfence();                       // release my writes
        unsigned r = atomicAdd(&g_cnt, 1u);
        if (r == NCTA - 1) {
            g_cnt = 0;
            __threadfence();                   // order reset before gen bump
            atomicAdd((unsigned*)&g_gen, 1u);
        } else {
            while ((int)(g_gen - target) < 0) __nanosleep(64);
        }
        __threadfence();                       // acquire others' writes
    }
    __syncthreads();
}

// ---------------- prep: softmax weights + gates ----------------
__global__ void prep_kernel(const float* __restrict__ logits,
                            const float* __restrict__ operands) {
    int bs = blockIdx.x;          // b*NS + s
    int b = bs >> 4, s = bs & 15;
    int lane = threadIdx.x;
    float v = (lane < NO) ? logits[bs * NO + lane] : -INFINITY;
    float m = v;
    #pragma unroll
    for (int off = 16; off > 0; off >>= 1)
        m = fmaxf(m, __shfl_xor_sync(0xffffffffu, m, off));
    float e = (lane < NO) ? expf(v - m) : 0.0f;
    float sum = e;
    #pragma unroll
    for (int off = 16; off > 0; off >>= 1)
        sum += __shfl_xor_sync(0xffffffffu, sum, off);
    if (lane < NO) g_w[s][b][lane] = e / sum;
    if (lane == 0) g_gate[s][b] = 1.0f / (1.0f + expf(-operands[bs * 4 + 3]));
}

// ---------------- convert op_kernels fp32 -> fp16 ----------------
__global__ void convert_kernel(const float* __restrict__ K) {
    size_t i = ((size_t)blockIdx.x * blockDim.x + threadIdx.x) * 8;
    float4 f0 = *(const float4*)(K + i);
    float4 f1 = *(const float4*)(K + i + 4);
    __half2* dst = (__half2*)(g_Kh + i);
    dst[0] = __floats2half2_rn(f0.x, f0.y);
    dst[1] = __floats2half2_rn(f0.z, f0.w);
    dst[2] = __floats2half2_rn(f1.x, f1.y);
    dst[3] = __floats2half2_rn(f1.z, f1.w);
}

// ---------------- persistent interpreter: all 16 steps in one kernel ----------------
// grid 248 = (31 opcodes) x (8 N-tiles), 256 threads.
// CTA(ks,ntile): partial[ks][b][n] = w[t][b][ks] * (h @ K_ks)[b, ntile-slice]
__global__ __launch_bounds__(256, 2) void npi_persistent(
    const float* __restrict__ signal, float* __restrict__ out) {
    const int bid = blockIdx.x;
    const int ks = bid >> 3;        // opcode  0..30
    const int ntile = bid & 7;      // N tile  0..7
    const int tid = threadIdx.x;
    const int wid = tid >> 5, lane = tid & 31;
    const int wm = wid & 1, wn = wid >> 1;

    __shared__ __half As[STAGES][64 * 40];
    __shared__ __half Bs[STAGES][32 * 136];
    __shared__ unsigned s_gen0;

    if (tid == 0) s_gen0 = g_gen;   // snapshot for replay-safe barriers
    __syncthreads();
    unsigned nbar = 0;

    // ---- init: h = signal (fp32 + fp16 copies) ----
    const int gidx = bid * 256 + tid;        // 0..63487; 32768 float2 items
    if (gidx < NB * ND / 2) {
        float2 s = ((const float2*)signal)[gidx];
        ((float2*)g_h)[gidx] = s;
        ((__half2*)g_hh)[gidx] = __floats2half2_rn(s.x, s.y);
    }
    grid_barrier(s_gen0 + ++nbar);

    const int k0 = ks * KCH;        // row base into g_Kh
    const int nbase = ntile * BN;
    const int arow = tid >> 2, ach = tid & 3;    // A loader: 64 rows x 4 chunks
    const int brow = tid >> 4, bch = tid & 15;   // B loader: 16 rows x 16 chunks (x2)
    float* pp = g_partial + (size_t)ks * NB * ND;

    #define LOAD_TILES(buf, d0) do {                                                 \
        cp_async16(smem_u32(&As[buf][arow * 40 + ach * 8]),                          \
                   g_hh + arow * ND + (d0) + ach * 8);                               \
        cp_async16(smem_u32(&Bs[buf][brow * 136 + bch * 8]),                         \
                   g_Kh + (size_t)(k0 + (d0) + brow) * ND + nbase + bch * 8);        \
        cp_async16(smem_u32(&Bs[buf][(brow + 16) * 136 + bch * 8]),                  \
                   g_Kh + (size_t)(k0 + (d0) + brow + 16) * ND + nbase + bch * 8);   \
    } while (0)

    for (int t = 0; t < NS; ++t) {
        float c[2][4][4];
        #pragma unroll
        for (int i = 0; i < 2; i++)
            #pragma unroll
            for (int j = 0; j < 4; j++)
                #pragma unroll
                for (int q = 0; q < 4; q++) c[i][j][q] = 0.0f;

        LOAD_TILES(0, 0);
        cp_commit();
        LOAD_TILES(1, BK);
        cp_commit();

        for (int it = 0; it < NIT; ++it) {
            const int buf = it % STAGES;
            cp_wait1();
            __syncthreads();

            if (it + 2 < NIT) {
                LOAD_TILES((it + 2) % STAGES, (it + 2) * BK);
            }
            cp_commit();

            #pragma unroll
            for (int kh = 0; kh < 2; ++kh) {
                uint32_t a[2][4];
                #pragma unroll
                for (int mf = 0; mf < 2; ++mf) {
                    uint32_t addr = smem_u32(
                        &As[buf][(wm * 32 + mf * 16 + (lane & 15)) * 40 + kh * 16 + (lane >> 4) * 8]);
                    ldm_x4(a[mf], addr);
                }
                uint32_t bb[2][4];
                #pragma unroll
                for (int np = 0; np < 2; ++np) {
                    uint32_t addr = smem_u32(
                        &Bs[buf][(kh * 16 + (lane & 15)) * 136 + wn * 32 + np * 16 + (lane >> 4) * 8]);
                    ldm_x4t(bb[np], addr);
                }
                #pragma unroll
                for (int mf = 0; mf < 2; ++mf)
                    #pragma unroll
                    for (int nf = 0; nf < 4; ++nf)
                        mma16816(c[mf][nf], a[mf], bb[nf >> 1][(nf & 1) * 2], bb[nf >> 1][(nf & 1) * 2 + 1]);
            }
            __syncthreads();
        }

        // epilogue: scale by w[t][b][ks] (fp32) and store partial
        #pragma unroll
        for (int mf = 0; mf < 2; ++mf) {
            const int m = wm * 32 + mf * 16 + (lane >> 2);
            const float wA = g_w[t][m][ks];
            const float wB = g_w[t][m + 8][ks];
            #pragma unroll
            for (int nf = 0; nf < 4; ++nf) {
                int n = nbase + wn * 32 + nf * 8 + (lane & 3) * 2;
                pp[(size_t)m * ND + n]           = wA * c[mf][nf][0];
                pp[(size_t)m * ND + n + 1]       = wA * c[mf][nf][1];
                pp[(size_t)(m + 8) * ND + n]     = wB * c[mf][nf][2];
                pp[(size_t)(m + 8) * ND + n + 1] = wB * c[mf][nf][3];
            }
        }
        grid_barrier(s_gen0 + ++nbar);

        // ---- update phase: reduce 31 partials, gate, refresh h ----
        if (gidx < NB * ND / 2) {
            const int b = gidx >> 9;       // 512 float2 per batch row
            float2 tr = make_float2(0.0f, 0.0f);
            #pragma unroll
            for (int o = 0; o < NO; ++o) {
                float2 p = ((const float2*)(g_partial + (size_t)o * NB * ND))[gidx];
                tr.x += p.x;
                tr.y += p.y;
            }
            const float g = g_gate[t][b];
            float2 h = ((const float2*)g_h)[gidx];
            float2 hn;
            hn.x = g * tr.x + (1.0f - g) * h.x;
            hn.y = g * tr.y + (1.0f - g) * h.y;
            if (t == NS - 1) {
                ((float2*)out)[gidx] = hn;
            } else {
                ((float2*)g_h)[gidx] = hn;
                ((__half2*)g_hh)[gidx] = __floats2half2_rn(hn.x, hn.y);
            }
        }
        if (t != NS - 1) grid_barrier(s_gen0 + ++nbar);
    }
}

// ---------------- launch ----------------
extern "C" void kernel_launch(void* const* d_in, const int* in_sizes, int n_in,
                              void* d_out, int out_size) {
    const float* logits   = (const float*)d_in[0];  // (64,16,31)
    const float* operands = (const float*)d_in[1];  // (64,16,4)
    const float* signal   = (const float*)d_in[2];  // (64,1024)
    const float* opk      = (const float*)d_in[3];  // (31,1024,1024)
    float* out = (float*)d_out;                     // (64,1024)

    prep_kernel<<<NB * NS, 32>>>(logits, operands);
    convert_kernel<<<(KTOT * ND) / 8 / 256, 256>>>(opk);
    npi_persistent<<<NCTA, 256>>>(signal, out);
}

// round 6
// speedup vs baseline: 1.1697x; 1.0027x over previous
#include <cuda_runtime.h>
#include <cuda_fp16.h>
#include <cstdint>
#include <cmath>

// Problem constants
#define NB 64          // batch
#define NS 16          // steps
#define NO 31          // opcodes
#define ND 1024        // hidden dim
#define KTOT (NO*ND)   // 31744
#define KCH ND         // 1024: one opcode per K-split
#define BK 32
#define NIT (KCH/BK)   // 32
#define BN 128
#define NTILES (ND/BN) // 8
#define STAGES 3
#define NCTA (NTILES*NO)   // 248

// ---------------- device scratch ----------------
__device__ __half  g_Kh[(size_t)KTOT * ND];        // 65 MB fp16 kernels [o*1024+d][n]
__device__ __half  g_hh[NB * ND];                  // fp16 hidden (GEMM A operand)
__device__ float   g_h[NB * ND];                   // fp32 hidden state
__device__ float   g_partial[NO * NB * ND];        // per-opcode partials (w applied)
__device__ float   g_w[NS][NB][NO];                // softmax weights
__device__ float   g_gate[NS][NB];                 // sigmoid gates
// hierarchical barrier state (monotone counters: replay-safe, no resets)
__device__ volatile unsigned g_gen;
__device__ unsigned g_cnt_sub[NTILES][64];         // 256B stride between counters
__device__ unsigned g_cnt_top;

// ---------------- helpers ----------------
__device__ __forceinline__ uint32_t smem_u32(const void* p) {
    return (uint32_t)__cvta_generic_to_shared(p);
}
__device__ __forceinline__ void cp_async16(uint32_t dst, const void* src) {
    asm volatile("cp.async.cg.shared.global [%0], [%1], 16;\n" :: "r"(dst), "l"(src));
}
__device__ __forceinline__ void cp_commit() {
    asm volatile("cp.async.commit_group;\n");
}
__device__ __forceinline__ void cp_wait1() {
    asm volatile("cp.async.wait_group 1;\n");
}
__device__ __forceinline__ void ldm_x4(uint32_t* r, uint32_t addr) {
    asm volatile("ldmatrix.sync.aligned.m8n8.x4.shared.b16 {%0,%1,%2,%3}, [%4];\n"
                 : "=r"(r[0]), "=r"(r[1]), "=r"(r[2]), "=r"(r[3]) : "r"(addr));
}
__device__ __forceinline__ void ldm_x4t(uint32_t* r, uint32_t addr) {
    asm volatile("ldmatrix.sync.aligned.m8n8.x4.trans.shared.b16 {%0,%1,%2,%3}, [%4];\n"
                 : "=r"(r[0]), "=r"(r[1]), "=r"(r[2]), "=r"(r[3]) : "r"(addr));
}
__device__ __forceinline__ void mma16816(float* c, const uint32_t* a, uint32_t b0, uint32_t b1) {
    asm volatile(
        "mma.sync.aligned.m16n8k16.row.col.f32.f16.f16.f32 "
        "{%0,%1,%2,%3}, {%4,%5,%6,%7}, {%8,%9}, {%0,%1,%2,%3};\n"
        : "+f"(c[0]), "+f"(c[1]), "+f"(c[2]), "+f"(c[3])
        : "r"(a[0]), "r"(a[1]), "r"(a[2]), "r"(a[3]), "r"(b0), "r"(b1));
}

// Hierarchical replay-safe grid barrier.
// sub = ntile group (31 CTAs each), then top (8 arrivals), then gen bump.
__device__ __forceinline__ void grid_barrier(int sub, unsigned target) {
    __syncthreads();
    if (threadIdx.x == 0) {
        __threadfence();                               // release my writes
        unsigned r = atomicAdd(&g_cnt_sub[sub][0], 1u) + 1u;
        if (r % NO == 0u) {                            // last of this sub-group
            unsigned r2 = atomicAdd(&g_cnt_top, 1u) + 1u;
            if (r2 % NTILES == 0u) {                   // last sub-group
                atomicAdd((unsigned*)&g_gen, 1u);
            }
        }
        while ((int)(g_gen - target) < 0) __nanosleep(32);
        __threadfence();                               // acquire others' writes
    }
    __syncthreads();
}

// ---------------- prep: softmax weights + gates ----------------
// 128 blocks x 256 threads; each warp handles one (b,s).
__global__ void prep_kernel(const float* __restrict__ logits,
                            const float* __restrict__ operands) {
    int bs = blockIdx.x * 8 + (threadIdx.x >> 5);   // 0..1023
    int b = bs >> 4, s = bs & 15;
    int lane = threadIdx.x & 31;
    float v = (lane < NO) ? logits[bs * NO + lane] : -INFINITY;
    float m = v;
    #pragma unroll
    for (int off = 16; off > 0; off >>= 1)
        m = fmaxf(m, __shfl_xor_sync(0xffffffffu, m, off));
    float e = (lane < NO) ? expf(v - m) : 0.0f;
    float sum = e;
    #pragma unroll
    for (int off = 16; off > 0; off >>= 1)
        sum += __shfl_xor_sync(0xffffffffu, sum, off);
    if (lane < NO) g_w[s][b][lane] = e / sum;
    if (lane == 0) g_gate[s][b] = 1.0f / (1.0f + expf(-operands[bs * 4 + 3]));
}

// ---------------- convert op_kernels fp32 -> fp16 ----------------
__global__ void convert_kernel(const float* __restrict__ K) {
    size_t i = ((size_t)blockIdx.x * blockDim.x + threadIdx.x) * 8;
    float4 f0 = *(const float4*)(K + i);
    float4 f1 = *(const float4*)(K + i + 4);
    __half2* dst = (__half2*)(g_Kh + i);
    dst[0] = __floats2half2_rn(f0.x, f0.y);
    dst[1] = __floats2half2_rn(f0.z, f0.w);
    dst[2] = __floats2half2_rn(f1.x, f1.y);
    dst[3] = __floats2half2_rn(f1.z, f1.w);
}

// ---------------- persistent interpreter: all 16 steps in one kernel ----------------
// grid 248 = (31 opcodes) x (8 N-tiles), 256 threads.
__global__ __launch_bounds__(256, 2) void npi_persistent(
    const float* __restrict__ signal, float* __restrict__ out) {
    const int bid = blockIdx.x;
    const int ks = bid >> 3;        // opcode  0..30
    const int ntile = bid & 7;      // N tile  0..7
    const int tid = threadIdx.x;
    const int wid = tid >> 5, lane = tid & 31;
    const int wm = wid & 1, wn = wid >> 1;

    __shared__ __half As[STAGES][64 * 40];
    __shared__ __half Bs[STAGES][32 * 136];
    __shared__ unsigned s_gen0;

    if (tid == 0) s_gen0 = g_gen;   // snapshot for replay-safe barriers
    __syncthreads();
    unsigned nbar = 0;

    // ---- init: h = signal (fp32 + fp16 copies) ----
    const int gidx = bid * 256 + tid;        // 32768 float2 items
    if (gidx < NB * ND / 2) {
        float2 s = ((const float2*)signal)[gidx];
        ((float2*)g_h)[gidx] = s;
        ((__half2*)g_hh)[gidx] = __floats2half2_rn(s.x, s.y);
    }
    grid_barrier(ntile, s_gen0 + ++nbar);

    const int k0 = ks * KCH;        // row base into g_Kh
    const int nbase = ntile * BN;
    const int arow = tid >> 2, ach = tid & 3;    // A loader: 64 rows x 4 chunks
    const int brow = tid >> 4, bch = tid & 15;   // B loader: 16 rows x 16 chunks (x2)
    float* pp = g_partial + (size_t)ks * NB * ND;

    #define LOAD_TILES(buf, d0) do {                                                 \
        cp_async16(smem_u32(&As[buf][arow * 40 + ach * 8]),                          \
                   g_hh + arow * ND + (d0) + ach * 8);                               \
        cp_async16(smem_u32(&Bs[buf][brow * 136 + bch * 8]),                         \
                   g_Kh + (size_t)(k0 + (d0) + brow) * ND + nbase + bch * 8);        \
        cp_async16(smem_u32(&Bs[buf][(brow + 16) * 136 + bch * 8]),                  \
                   g_Kh + (size_t)(k0 + (d0) + brow + 16) * ND + nbase + bch * 8);   \
    } while (0)

    for (int t = 0; t < NS; ++t) {
        float c[2][4][4];
        #pragma unroll
        for (int i = 0; i < 2; i++)
            #pragma unroll
            for (int j = 0; j < 4; j++)
                #pragma unroll
                for (int q = 0; q < 4; q++) c[i][j][q] = 0.0f;

        LOAD_TILES(0, 0);
        cp_commit();
        LOAD_TILES(1, BK);
        cp_commit();

        for (int it = 0; it < NIT; ++it) {
            const int buf = it % STAGES;
            cp_wait1();
            __syncthreads();        // single sync per iteration (prefetch-overwrite safe)

            if (it + 2 < NIT) {
                LOAD_TILES((it + 2) % STAGES, (it + 2) * BK);
            }
            cp_commit();

            #pragma unroll
            for (int kh = 0; kh < 2; ++kh) {
                uint32_t a[2][4];
                #pragma unroll
                for (int mf = 0; mf < 2; ++mf) {
                    uint32_t addr = smem_u32(
                        &As[buf][(wm * 32 + mf * 16 + (lane & 15)) * 40 + kh * 16 + (lane >> 4) * 8]);
                    ldm_x4(a[mf], addr);
                }
                uint32_t bb[2][4];
                #pragma unroll
                for (int np = 0; np < 2; ++np) {
                    uint32_t addr = smem_u32(
                        &Bs[buf][(kh * 16 + (lane & 15)) * 136 + wn * 32 + np * 16 + (lane >> 4) * 8]);
                    ldm_x4t(bb[np], addr);
                }
                #pragma unroll
                for (int mf = 0; mf < 2; ++mf)
                    #pragma unroll
                    for (int nf = 0; nf < 4; ++nf)
                        mma16816(c[mf][nf], a[mf], bb[nf >> 1][(nf & 1) * 2], bb[nf >> 1][(nf & 1) * 2 + 1]);
            }
        }
        __syncthreads();   // protect stage buffers before next step reuses stage 0/1

        // epilogue: scale by w[t][b][ks] (fp32) and store partial
        #pragma unroll
        for (int mf = 0; mf < 2; ++mf) {
            const int m = wm * 32 + mf * 16 + (lane >> 2);
            const float wA = g_w[t][m][ks];
            const float wB = g_w[t][m + 8][ks];
            #pragma unroll
            for (int nf = 0; nf < 4; ++nf) {
                int n = nbase + wn * 32 + nf * 8 + (lane & 3) * 2;
                pp[(size_t)m * ND + n]           = wA * c[mf][nf][0];
                pp[(size_t)m * ND + n + 1]       = wA * c[mf][nf][1];
                pp[(size_t)(m + 8) * ND + n]     = wB * c[mf][nf][2];
                pp[(size_t)(m + 8) * ND + n + 1] = wB * c[mf][nf][3];
            }
        }
        grid_barrier(ntile, s_gen0 + ++nbar);

        // ---- update phase: reduce 31 partials, gate, refresh h ----
        if (gidx < NB * ND / 2) {
            const int b = gidx >> 9;       // 512 float2 per batch row
            float2 tr = make_float2(0.0f, 0.0f);
            #pragma unroll
            for (int o = 0; o < NO; ++o) {
                float2 p = ((const float2*)(g_partial + (size_t)o * NB * ND))[gidx];
                tr.x += p.x;
                tr.y += p.y;
            }
            const float g = g_gate[t][b];
            float2 h = ((const float2*)g_h)[gidx];
            float2 hn;
            hn.x = g * tr.x + (1.0f - g) * h.x;
            hn.y = g * tr.y + (1.0f - g) * h.y;
            if (t == NS - 1) {
                ((float2*)out)[gidx] = hn;
            } else {
                ((float2*)g_h)[gidx] = hn;
                ((__half2*)g_hh)[gidx] = __floats2half2_rn(hn.x, hn.y);
            }
        }
        if (t != NS - 1) grid_barrier(ntile, s_gen0 + ++nbar);
    }
}

// ---------------- launch ----------------
extern "C" void kernel_launch(void* const* d_in, const int* in_sizes, int n_in,
                              void* d_out, int out_size) {
    const float* logits   = (const float*)d_in[0];  // (64,16,31)
    const float* operands = (const float*)d_in[1];  // (64,16,4)
    const float* signal   = (const float*)d_in[2];  // (64,1024)
    const float* opk      = (const float*)d_in[3];  // (31,1024,1024)
    float* out = (float*)d_out;                     // (64,1024)

    prep_kernel<<<128, 256>>>(logits, operands);
    convert_kernel<<<(KTOT * ND) / 8 / 256, 256>>>(opk);
    npi_persistent<<<NCTA, 256>>>(signal, out);
}